// round 7
// baseline (speedup 1.0000x reference)
#include <cuda_runtime.h>
#include <cuda_bf16.h>

// Problem constants (from reference)
#define T_DIM 64
#define S_DIM 512
#define X_DIM 16
#define Y_DIM 16
#define G_DIM 64
#define NBLK 32
// MAX_CX = MAX_CY = LAM = 1.0

// Algebra: Phi = trans @ 0 = 0 (trans dead); J = pi0 @ V[0] (only t=0 live);
// sum_x px[x]*(x+y) = mx + y.
// J = sum_s pi0[s] * sum_y w[s,y] * (A[s,y] + mx + y)
//   w[s,y] = sum_g py[y,g]*obv[s,g],  A[s,y] = sum_x px[x]*loss[s,x,y]

__device__ float g_partial[NBLK];
__device__ unsigned int g_ticket;   // zero-init; self-resetting each launch

__global__ void __launch_bounds__(256, 1)
v1_kernel(const float* __restrict__ policy_var,
          const float* __restrict__ obv,
          const float* __restrict__ loss_table,
          const float* __restrict__ pi0,
          float* __restrict__ out)
{
    // Padded layouts: conflict-free LDS + 16B-aligned rows for float4 stores.
    __shared__ float s_obv [16][68];   // stride 68  (272B,  mod16=0; mod32=4 banks)
    __shared__ float s_loss[16][260];  // stride 260 (1040B, mod16=0; mod32=4 banks)
    __shared__ float s_pyraw[1024];
    __shared__ float s_py  [16][69];   // stride 69: 5y mod 32 distinct for y<16
    __shared__ float s_pv0[16];
    __shared__ float s_pi0[16];
    __shared__ float s_px[16];
    __shared__ float s_mx;
    __shared__ float s_red[16];
    __shared__ bool  s_last;

    const int tid = threadIdx.x;
    const int blk = blockIdx.x;

    // ================= Phase 1: one burst of vectorized global loads ========
    // obv slice [16 s][64 g] = 1024 floats = 256 float4 (1 per thread)
    {
        float4 v = ((const float4*)(obv + blk * 16 * G_DIM))[tid];
        const int f = tid * 4;
        *(float4*)&s_obv[f >> 6][f & 63] = v;
    }
    // loss slice [16 s][256 xy] = 4096 floats = 1024 float4 (4 per thread)
    {
        const float4* src = (const float4*)(loss_table + blk * 16 * (X_DIM * Y_DIM));
        #pragma unroll
        for (int k = 0; k < 4; k++) {
            float4 v = src[tid + k * 256];
            const int f = (tid + k * 256) * 4;
            *(float4*)&s_loss[f >> 8][f & 255] = v;
        }
    }
    // py raw params: policy_var[1024..2047] = 256 float4 (1 per thread)
    *(float4*)&s_pyraw[tid * 4] = ((const float4*)(policy_var + T_DIM * X_DIM))[tid];
    // px row 0 (16 floats) + pi0 slice (16 floats)
    if (tid < 4)
        *(float4*)&s_pv0[tid * 4] = ((const float4*)policy_var)[tid];
    else if (tid < 8)
        *(float4*)&s_pi0[(tid - 4) * 4] = ((const float4*)(pi0 + blk * 16))[tid - 4];
    __syncthreads();

    // ================= Phase 2: softmaxes (different warps, concurrent) =====
    if (tid == 0) {                       // warp 0: px softmax + mx = E_px[x]
        float v[X_DIM];
        float m = -1e30f;
        #pragma unroll
        for (int x = 0; x < X_DIM; x++) { v[x] = s_pv0[x]; m = fmaxf(m, v[x]); }
        float sum = 0.f;
        #pragma unroll
        for (int x = 0; x < X_DIM; x++) { v[x] = __expf(v[x] - m); sum += v[x]; }
        const float inv = 1.f / sum;
        float mx = 0.f;
        #pragma unroll
        for (int x = 0; x < X_DIM; x++) {
            const float p = v[x] * inv;
            s_px[x] = p;
            mx += p * (float)x;
        }
        s_mx = mx;
    }
    if (tid >= 64 && tid < 128) {         // warps 2-3: py softmax per g-column
        const int g = tid - 64;
        float v[Y_DIM];
        float m = -1e30f;
        #pragma unroll
        for (int y = 0; y < Y_DIM; y++) { // lanes g=0..31: banks g mod 32 distinct
            v[y] = s_pyraw[y * G_DIM + g];
            m = fmaxf(m, v[y]);
        }
        float sum = 0.f;
        #pragma unroll
        for (int y = 0; y < Y_DIM; y++) { v[y] = __expf(v[y] - m); sum += v[y]; }
        const float inv = 1.f / sum;
        #pragma unroll
        for (int y = 0; y < Y_DIM; y++) s_py[y][g] = v[y] * inv;
    }
    __syncthreads();

    // ================= Phase 3: per-thread (si, y) dot products =============
    const int si = tid >> 4;     // 0..15  local s
    const int y  = tid & 15;     // 0..15

    // w = sum_g py[y,g] * obv[s,g]  — all smem, conflict-free, fully unrolled
    float w = 0.f;
    #pragma unroll
    for (int g = 0; g < G_DIM; g++) w = fmaf(s_py[y][g], s_obv[si][g], w);

    // A = sum_x px[x] * loss[s,x,y]
    float A = 0.f;
    #pragma unroll
    for (int x = 0; x < X_DIM; x++) A = fmaf(s_px[x], s_loss[si][x * Y_DIM + y], A);

    float val = w * (A + s_mx + (float)y);

    // reduce over the 16 y-lanes
    #pragma unroll
    for (int off = 8; off >= 1; off >>= 1)
        val += __shfl_xor_sync(0xFFFFFFFFu, val, off);

    if ((tid & 15) == 0) s_red[si] = val * s_pi0[si];
    __syncthreads();

    // ================= Phase 4: deterministic inter-CTA reduction ===========
    if (tid == 0) {
        float total = 0.f;
        #pragma unroll
        for (int i = 0; i < 16; i++) total += s_red[i];
        g_partial[blk] = total;
        __threadfence();                       // release partial before ticket
        unsigned int t = atomicAdd(&g_ticket, 1u);
        s_last = (t == NBLK - 1);
    }
    __syncthreads();

    if (s_last && tid == 0) {
        const volatile float* vp = g_partial;  // acquire: force L2 reads
        float total = 0.f;
        #pragma unroll
        for (int i = 0; i < NBLK; i++) total += vp[i];
        out[0] = total;
        g_ticket = 0u;                         // self-reset for next replay
    }
}

extern "C" void kernel_launch(void* const* d_in, const int* in_sizes, int n_in,
                              void* d_out, int out_size)
{
    // metadata order: policy_var, trans, obv, loss_table, pi_0
    const float* policy_var = (const float*)d_in[0];
    // d_in[1] = trans: provably unused (Phi == 0)
    const float* obv        = (const float*)d_in[2];
    const float* loss_table = (const float*)d_in[3];
    const float* pi0        = (const float*)d_in[4];
    float* out = (float*)d_out;

    v1_kernel<<<NBLK, 256>>>(policy_var, obv, loss_table, pi0, out);
}